// round 3
// baseline (speedup 1.0000x reference)
#include <cuda_runtime.h>
#include <cstdint>

#define NN 50000
#define EE 100000
#define KNODE 544   /* 512 x-dims + 10 PE dims, padded to 17*32 */

// ---------------- scratch (device globals; no allocations allowed) ----------
__device__ float g_G[(size_t)NN * 1024];      // [n][0:512]=G_src, [512:1024]=G_dst
__device__ float g_Wnode[KNODE * 1024];       // tf32-rounded node weights
__device__ float g_Wqa[1024 * 512];           // tf32-rounded [q|attr] weights
__device__ float g_p[NN * 10];                // PE features: topic,f1,f2,r1,r2 (2 each)
__device__ float g_deg_in[NN];
__device__ float g_deg_out[NN];
__device__ int   g_flag[NN];                  // 1 = all-zero row -> use ne_emb

// ---------------- helpers ---------------------------------------------------
__device__ __forceinline__ unsigned tf32_bits(float f) {
    unsigned u;
    asm("cvt.rna.tf32.f32 %0, %1;" : "=r"(u) : "f"(f));
    return u;
}
__device__ __forceinline__ float tf32r(float f) { return __uint_as_float(tf32_bits(f)); }

__device__ __forceinline__ void mma_tf32(float* c, const unsigned* a, const unsigned* b) {
    asm volatile(
        "mma.sync.aligned.m16n8k8.row.col.f32.tf32.tf32.f32 "
        "{%0,%1,%2,%3}, {%4,%5,%6,%7}, {%8,%9}, {%0,%1,%2,%3};\n"
        : "+f"(c[0]), "+f"(c[1]), "+f"(c[2]), "+f"(c[3])
        : "r"(a[0]), "r"(a[1]), "r"(a[2]), "r"(a[3]), "r"(b[0]), "r"(b[1]));
}

// ---------------- small prep kernels ----------------------------------------
// W1 row map: q:0..511 | src.x:512..1023 | src.pe:1024..1033 | attr:1034..1545
//             dst.x:1546..2057 | dst.pe:2058..2067
__global__ void prep_wnode(const float* __restrict__ W1) {
    int idx = blockIdx.x * 256 + threadIdx.x;
    if (idx >= KNODE * 1024) return;
    int k = idx >> 10, j = idx & 1023;
    int jj = j & 511;
    bool hi = (j >= 512);  // dst block
    float v = 0.f;
    if (k < 512)       v = W1[(size_t)((hi ? 1546 : 512) + k) * 512 + jj];
    else if (k < 522)  v = W1[(size_t)((hi ? 2058 : 1024) + (k - 512)) * 512 + jj];
    g_Wnode[idx] = tf32r(v);
}

__global__ void prep_wqa(const float* __restrict__ W1) {
    int idx = blockIdx.x * 256 + threadIdx.x;
    if (idx >= 1024 * 512) return;
    int k = idx >> 9, j = idx & 511;
    int row = (k < 512) ? k : (1034 + (k - 512));
    g_Wqa[idx] = tf32r(W1[(size_t)row * 512 + j]);
}

__global__ void flag_kernel(const float* __restrict__ x) {
    int n = blockIdx.x * 8 + (threadIdx.x >> 5);
    int lane = threadIdx.x & 31;
    if (n >= NN) return;
    bool nz = false;
    #pragma unroll
    for (int i = 0; i < 16; ++i)
        nz |= (x[(size_t)n * 512 + lane + 32 * i] != 0.f);
    nz = __any_sync(0xffffffffu, nz);
    if (lane == 0) g_flag[n] = nz ? 0 : 1;
}

__global__ void init_nodes(const float* __restrict__ topic) {
    int n = blockIdx.x * 256 + threadIdx.x;
    if (n >= NN) return;
    g_p[n * 10 + 0] = topic[n * 2 + 0];
    g_p[n * 10 + 1] = topic[n * 2 + 1];
    #pragma unroll
    for (int c = 2; c < 10; ++c) g_p[n * 10 + c] = 0.f;
    g_deg_in[n] = 0.f;
    g_deg_out[n] = 0.f;
}

__global__ void out_init(float* __restrict__ out, const float* __restrict__ b2) {
    int e = blockIdx.x * 256 + threadIdx.x;
    if (e < EE) out[e] = b2[0];
}

__global__ void deg_kernel(const int* __restrict__ src, const int* __restrict__ dst) {
    int e = blockIdx.x * 256 + threadIdx.x;
    if (e >= EE) return;
    atomicAdd(&g_deg_in[dst[e]], 1.f);
    atomicAdd(&g_deg_out[src[e]], 1.f);
}

// round 1: fwd reads topic (cols 0,1) -> cols 2,3 ; rev -> cols 6,7
__global__ void conv1(const int* __restrict__ src, const int* __restrict__ dst) {
    int e = blockIdx.x * 256 + threadIdx.x;
    if (e >= EE) return;
    int s = src[e], d = dst[e];
    atomicAdd(&g_p[d * 10 + 2], g_p[s * 10 + 0]);
    atomicAdd(&g_p[d * 10 + 3], g_p[s * 10 + 1]);
    atomicAdd(&g_p[s * 10 + 6], g_p[d * 10 + 0]);
    atomicAdd(&g_p[s * 10 + 7], g_p[d * 10 + 1]);
}

__global__ void norm1() {
    int n = blockIdx.x * 256 + threadIdx.x;
    if (n >= NN) return;
    float di = fmaxf(g_deg_in[n], 1.f), dv = fmaxf(g_deg_out[n], 1.f);
    g_p[n * 10 + 2] /= di;  g_p[n * 10 + 3] /= di;
    g_p[n * 10 + 6] /= dv;  g_p[n * 10 + 7] /= dv;
}

// round 2: fwd reads cols 2,3 -> 4,5 ; rev reads 6,7 -> 8,9
__global__ void conv2(const int* __restrict__ src, const int* __restrict__ dst) {
    int e = blockIdx.x * 256 + threadIdx.x;
    if (e >= EE) return;
    int s = src[e], d = dst[e];
    atomicAdd(&g_p[d * 10 + 4], g_p[s * 10 + 2]);
    atomicAdd(&g_p[d * 10 + 5], g_p[s * 10 + 3]);
    atomicAdd(&g_p[s * 10 + 8], g_p[d * 10 + 6]);
    atomicAdd(&g_p[s * 10 + 9], g_p[d * 10 + 7]);
}

__global__ void norm2() {
    int n = blockIdx.x * 256 + threadIdx.x;
    if (n >= NN) return;
    float di = fmaxf(g_deg_in[n], 1.f), dv = fmaxf(g_deg_out[n], 1.f);
    g_p[n * 10 + 4] /= di;  g_p[n * 10 + 5] /= di;
    g_p[n * 10 + 8] /= dv;  g_p[n * 10 + 9] /= dv;
}

// ---------------- node GEMM: G[N,1024] = [x' | p] @ Wnode --------------------
__global__ __launch_bounds__(256, 2) void node_gemm(
    const float* __restrict__ x, const float* __restrict__ ne_emb)
{
    __shared__ float As[128][36];
    __shared__ float Bs[32][136];

    const int tid = threadIdx.x;
    const int m0 = blockIdx.x * 128;
    const int n0 = blockIdx.y * 128;
    const int warp = tid >> 5, lane = tid & 31;
    const int wm = warp & 1, wn = warp >> 1;
    const int g = lane >> 2, t = lane & 3;

    float acc[4][4][4];
    #pragma unroll
    for (int i = 0; i < 4; ++i)
        #pragma unroll
        for (int j = 0; j < 4; ++j)
            #pragma unroll
            for (int k = 0; k < 4; ++k) acc[i][j][k] = 0.f;

    #pragma unroll 1
    for (int kt = 0; kt < KNODE / 32; ++kt) {
        const int kbase = kt * 32;
        __syncthreads();
        #pragma unroll
        for (int i = 0; i < 16; ++i) {
            int idx = i * 256 + tid;
            int row = idx >> 5, kk = idx & 31;
            int n = m0 + row;
            int kg = kbase + kk;
            float v = 0.f;
            if (n < NN) {
                if (kg < 512)      v = g_flag[n] ? ne_emb[kg] : x[(size_t)n * 512 + kg];
                else if (kg < 522) v = g_p[n * 10 + (kg - 512)];
            }
            As[row][kk] = tf32r(v);
        }
        #pragma unroll
        for (int i = 0; i < 4; ++i) {
            int idx = i * 256 + tid;
            int row = idx >> 5, c4 = idx & 31;
            *(float4*)&Bs[row][c4 * 4] =
                *(const float4*)&g_Wnode[(size_t)(kbase + row) * 1024 + n0 + c4 * 4];
        }
        __syncthreads();
        #pragma unroll
        for (int ks = 0; ks < 4; ++ks) {
            const int k0 = ks * 8;
            unsigned a[4][4], b[4][2];
            #pragma unroll
            for (int mf = 0; mf < 4; ++mf) {
                int r = wm * 64 + mf * 16;
                a[mf][0] = __float_as_uint(As[r + g][k0 + t]);
                a[mf][1] = __float_as_uint(As[r + g + 8][k0 + t]);
                a[mf][2] = __float_as_uint(As[r + g][k0 + t + 4]);
                a[mf][3] = __float_as_uint(As[r + g + 8][k0 + t + 4]);
            }
            #pragma unroll
            for (int nf = 0; nf < 4; ++nf) {
                int c = wn * 32 + nf * 8 + g;
                b[nf][0] = __float_as_uint(Bs[k0 + t][c]);
                b[nf][1] = __float_as_uint(Bs[k0 + t + 4][c]);
            }
            #pragma unroll
            for (int mf = 0; mf < 4; ++mf)
                #pragma unroll
                for (int nf = 0; nf < 4; ++nf)
                    mma_tf32(acc[mf][nf], a[mf], b[nf]);
        }
    }

    #pragma unroll
    for (int mf = 0; mf < 4; ++mf) {
        #pragma unroll
        for (int half = 0; half < 2; ++half) {
            int r = wm * 64 + mf * 16 + g + half * 8;
            int n = m0 + r;
            if (n < NN) {
                float* Gp = g_G + (size_t)n * 1024 + n0;
                #pragma unroll
                for (int nf = 0; nf < 4; ++nf) {
                    int cj = wn * 32 + nf * 8 + 2 * t;
                    float2 v = make_float2(acc[mf][nf][half * 2 + 0],
                                           acc[mf][nf][half * 2 + 1]);
                    *(float2*)&Gp[cj] = v;
                }
            }
        }
    }
}

// ---------------- edge GEMM + fused epilogue ---------------------------------
__global__ __launch_bounds__(256, 2) void edge_gemm(
    const float* __restrict__ q_emb, const float* __restrict__ edge_attr,
    const int* __restrict__ src, const int* __restrict__ dst,
    const float* __restrict__ b1, const float* __restrict__ W2,
    float* __restrict__ out)
{
    __shared__ float As[128][36];
    __shared__ float Bs[32][136];
    __shared__ float sB1[128];
    __shared__ float sW2[128];

    const int tid = threadIdx.x;
    const int m0 = blockIdx.x * 128;
    const int n0 = blockIdx.y * 128;
    const int warp = tid >> 5, lane = tid & 31;
    const int wm = warp & 1, wn = warp >> 1;
    const int g = lane >> 2, t = lane & 3;

    if (tid < 128) { sB1[tid] = b1[n0 + tid]; sW2[tid] = W2[n0 + tid]; }

    float acc[4][4][4];
    #pragma unroll
    for (int i = 0; i < 4; ++i)
        #pragma unroll
        for (int j = 0; j < 4; ++j)
            #pragma unroll
            for (int k = 0; k < 4; ++k) acc[i][j][k] = 0.f;

    #pragma unroll 1
    for (int kt = 0; kt < 32; ++kt) {
        const int kbase = kt * 32;
        __syncthreads();
        #pragma unroll
        for (int i = 0; i < 4; ++i) {
            int f4 = i * 256 + tid;            // 0..1023 float4 slots
            int row = f4 >> 3, c4 = f4 & 7;
            int e = m0 + row;
            int kg = kbase + c4 * 4;
            float4 v = make_float4(0.f, 0.f, 0.f, 0.f);
            if (e < EE) {
                const float* p = (kg < 512) ? (q_emb + (size_t)e * 512 + kg)
                                            : (edge_attr + (size_t)e * 512 + (kg - 512));
                v = *(const float4*)p;
            }
            float4 r;
            r.x = tf32r(v.x); r.y = tf32r(v.y); r.z = tf32r(v.z); r.w = tf32r(v.w);
            *(float4*)&As[row][c4 * 4] = r;
        }
        #pragma unroll
        for (int i = 0; i < 4; ++i) {
            int f4 = i * 256 + tid;
            int row = f4 >> 5, c4 = f4 & 31;
            *(float4*)&Bs[row][c4 * 4] =
                *(const float4*)&g_Wqa[(size_t)(kbase + row) * 512 + n0 + c4 * 4];
        }
        __syncthreads();
        #pragma unroll
        for (int ks = 0; ks < 4; ++ks) {
            const int k0 = ks * 8;
            unsigned a[4][4], b[4][2];
            #pragma unroll
            for (int mf = 0; mf < 4; ++mf) {
                int r = wm * 64 + mf * 16;
                a[mf][0] = __float_as_uint(As[r + g][k0 + t]);
                a[mf][1] = __float_as_uint(As[r + g + 8][k0 + t]);
                a[mf][2] = __float_as_uint(As[r + g][k0 + t + 4]);
                a[mf][3] = __float_as_uint(As[r + g + 8][k0 + t + 4]);
            }
            #pragma unroll
            for (int nf = 0; nf < 4; ++nf) {
                int c = wn * 32 + nf * 8 + g;
                b[nf][0] = __float_as_uint(Bs[k0 + t][c]);
                b[nf][1] = __float_as_uint(Bs[k0 + t + 4][c]);
            }
            #pragma unroll
            for (int mf = 0; mf < 4; ++mf)
                #pragma unroll
                for (int nf = 0; nf < 4; ++nf)
                    mma_tf32(acc[mf][nf], a[mf], b[nf]);
        }
    }

    // epilogue: z = acc + b1 + G_s[src] + G_d[dst]; relu; dot with W2; atomic add
    #pragma unroll
    for (int mf = 0; mf < 4; ++mf) {
        #pragma unroll
        for (int half = 0; half < 2; ++half) {
            int r = wm * 64 + mf * 16 + g + half * 8;
            int e = m0 + r;
            float rowsum = 0.f;
            if (e < EE) {
                int s = src[e], d = dst[e];
                const float* Gs = g_G + (size_t)s * 1024 + n0;
                const float* Gd = g_G + (size_t)d * 1024 + 512 + n0;
                #pragma unroll
                for (int nf = 0; nf < 4; ++nf) {
                    #pragma unroll
                    for (int p = 0; p < 2; ++p) {
                        int cj = wn * 32 + nf * 8 + 2 * t + p;
                        float z = acc[mf][nf][half * 2 + p] + sB1[cj] + Gs[cj] + Gd[cj];
                        z = fmaxf(z, 0.f);
                        rowsum = fmaf(z, sW2[cj], rowsum);
                    }
                }
            }
            rowsum += __shfl_xor_sync(0xffffffffu, rowsum, 1);
            rowsum += __shfl_xor_sync(0xffffffffu, rowsum, 2);
            if (t == 0 && e < EE) atomicAdd(out + e, rowsum);
        }
    }
}

// ---------------- launch ------------------------------------------------------
extern "C" void kernel_launch(void* const* d_in, const int* in_sizes, int n_in,
                              void* d_out, int out_size) {
    const float* x     = (const float*)d_in[0];
    const int*   ei    = (const int*)d_in[1];
    const float* attr  = (const float*)d_in[2];
    const float* topic = (const float*)d_in[3];
    const float* qemb  = (const float*)d_in[4];
    const float* ne    = (const float*)d_in[5];
    const float* W1    = (const float*)d_in[6];
    const float* b1    = (const float*)d_in[7];
    const float* W2    = (const float*)d_in[8];
    const float* b2    = (const float*)d_in[9];
    float* out = (float*)d_out;
    const int* src = ei;
    const int* dst = ei + EE;

    prep_wnode<<<(KNODE * 1024 + 255) / 256, 256>>>(W1);
    prep_wqa<<<(1024 * 512 + 255) / 256, 256>>>(W1);
    flag_kernel<<<(NN + 7) / 8, 256>>>(x);
    init_nodes<<<(NN + 255) / 256, 256>>>(topic);
    out_init<<<(EE + 255) / 256, 256>>>(out, b2);
    deg_kernel<<<(EE + 255) / 256, 256>>>(src, dst);
    conv1<<<(EE + 255) / 256, 256>>>(src, dst);
    norm1<<<(NN + 255) / 256, 256>>>();
    conv2<<<(EE + 255) / 256, 256>>>(src, dst);
    norm2<<<(NN + 255) / 256, 256>>>();
    node_gemm<<<dim3((NN + 127) / 128, 8), 256>>>(x, ne);
    edge_gemm<<<dim3((EE + 127) / 128, 4), 256>>>(qemb, attr, src, dst, b1, W2, out);
}

// round 4
// speedup vs baseline: 2.4354x; 2.4354x over previous
#include <cuda_runtime.h>
#include <cstdint>

#define NN 50000
#define EE 100000
#define KNODE 544          /* 512 x-dims + 10 PE dims + 22 zero pad */

// tiles
#define BM 128
#define BN 256
#define BK 32
#define AS_STRIDE 36       /* 32 + 4 pad, 144B rows (16B aligned) */
#define BS_STRIDE 264      /* 256 + 8 pad, 1056B rows (16B aligned) */
#define ABUF (BM * AS_STRIDE)
#define BBUF (BK * BS_STRIDE)
#define SMEM_BYTES ((2 * ABUF + 2 * BBUF) * 4)

// ---------------- scratch (device globals; no runtime allocations) ----------
__device__ float g_G[(size_t)NN * 1024];        // [n][0:512]=src-proj, [512:1024]=dst-proj
__device__ float g_Xp[(size_t)NN * KNODE];      // prepared node features (tf32-rna)
__device__ float g_Wnode[KNODE * 1024];         // tf32-rna node weights
__device__ float g_Wqa[1024 * 512];             // tf32-rna [q|attr] weights
__device__ float g_p[NN * 10];                  // PE raw sums
__device__ float g_deg_in[NN];
__device__ float g_deg_out[NN];

// ---------------- helpers ---------------------------------------------------
__device__ __forceinline__ float tf32r(float f) {
    unsigned u;
    asm("cvt.rna.tf32.f32 %0, %1;" : "=r"(u) : "f"(f));
    return __uint_as_float(u);
}

__device__ __forceinline__ void mma_tf32(float* c, const unsigned* a, const unsigned* b) {
    asm volatile(
        "mma.sync.aligned.m16n8k8.row.col.f32.tf32.tf32.f32 "
        "{%0,%1,%2,%3}, {%4,%5,%6,%7}, {%8,%9}, {%0,%1,%2,%3};\n"
        : "+f"(c[0]), "+f"(c[1]), "+f"(c[2]), "+f"(c[3])
        : "r"(a[0]), "r"(a[1]), "r"(a[2]), "r"(a[3]), "r"(b[0]), "r"(b[1]));
}

__device__ __forceinline__ void cp16(float* smem_dst, const float* gmem_src, int bytes) {
    unsigned d = (unsigned)__cvta_generic_to_shared(smem_dst);
    asm volatile("cp.async.cg.shared.global [%0], [%1], 16, %2;"
                 :: "r"(d), "l"(gmem_src), "r"(bytes));
}
__device__ __forceinline__ void cp_commit() {
    asm volatile("cp.async.commit_group;" ::: "memory");
}

// ---------------- prep: pack & tf32-round both weight blocks ----------------
// W1 row map: q:0..511 | src.x:512..1023 | src.pe:1024..1033 | attr:1034..1545
//             dst.x:1546..2057 | dst.pe:2058..2067
__global__ void prep_w(const float* __restrict__ W1) {
    int idx = blockIdx.x * 256 + threadIdx.x;
    if (idx < KNODE * 1024) {
        int k = idx >> 10, j = idx & 1023;
        int jj = j & 511;
        bool hi = (j >= 512);
        float v = 0.f;
        if (k < 512)      v = W1[(size_t)((hi ? 1546 : 512) + k) * 512 + jj];
        else if (k < 522) v = W1[(size_t)((hi ? 2058 : 1024) + (k - 512)) * 512 + jj];
        g_Wnode[idx] = tf32r(v);
    } else {
        int i2 = idx - KNODE * 1024;
        if (i2 >= 1024 * 512) return;
        int k = i2 >> 9, j = i2 & 511;
        int row = (k < 512) ? k : (1034 + (k - 512));
        g_Wqa[i2] = tf32r(W1[(size_t)row * 512 + j]);
    }
}

// ---------------- init: PE seed + degree zero + out = b2 ---------------------
__global__ void init_all(const float* __restrict__ topic,
                         const float* __restrict__ b2, float* __restrict__ out) {
    int idx = blockIdx.x * 256 + threadIdx.x;
    if (idx < NN) {
        g_p[idx * 10 + 0] = topic[idx * 2 + 0];
        g_p[idx * 10 + 1] = topic[idx * 2 + 1];
        #pragma unroll
        for (int c = 2; c < 10; ++c) g_p[idx * 10 + c] = 0.f;
        g_deg_in[idx] = 0.f;
        g_deg_out[idx] = 0.f;
    }
    if (idx < EE) out[idx] = b2[0];
}

// round 1 sums + degrees. fwd topic -> cols 2,3 (at dst); rev -> cols 6,7 (at src)
__global__ void conv1(const int* __restrict__ srcI, const int* __restrict__ dstI) {
    int e = blockIdx.x * 256 + threadIdx.x;
    if (e >= EE) return;
    int s = srcI[e], d = dstI[e];
    atomicAdd(&g_p[d * 10 + 2], g_p[s * 10 + 0]);
    atomicAdd(&g_p[d * 10 + 3], g_p[s * 10 + 1]);
    atomicAdd(&g_p[s * 10 + 6], g_p[d * 10 + 0]);
    atomicAdd(&g_p[s * 10 + 7], g_p[d * 10 + 1]);
    atomicAdd(&g_deg_in[d], 1.f);
    atomicAdd(&g_deg_out[s], 1.f);
}

// round 2 sums with round-1 normalization folded in.
// fwd: reads normalized cols 2,3 of src -> adds to 4,5 of dst
// rev: reads normalized cols 6,7 of dst -> adds to 8,9 of src
__global__ void conv2(const int* __restrict__ srcI, const int* __restrict__ dstI) {
    int e = blockIdx.x * 256 + threadIdx.x;
    if (e >= EE) return;
    int s = srcI[e], d = dstI[e];
    float inv_s = 1.f / fmaxf(g_deg_in[s], 1.f);
    float inv_d = 1.f / fmaxf(g_deg_out[d], 1.f);
    atomicAdd(&g_p[d * 10 + 4], g_p[s * 10 + 2] * inv_s);
    atomicAdd(&g_p[d * 10 + 5], g_p[s * 10 + 3] * inv_s);
    atomicAdd(&g_p[s * 10 + 8], g_p[d * 10 + 6] * inv_d);
    atomicAdd(&g_p[s * 10 + 9], g_p[d * 10 + 7] * inv_d);
}

// ---------------- prepare node features: x' | normalized PE | pad, tf32-rna --
__global__ void prep_xp(const float* __restrict__ x, const float* __restrict__ ne) {
    int n = (blockIdx.x * 256 + threadIdx.x) >> 5;
    int lane = threadIdx.x & 31;
    if (n >= NN) return;
    const float4* xr = (const float4*)(x + (size_t)n * 512);
    float4 v[4];
    bool nz = false;
    #pragma unroll
    for (int i = 0; i < 4; ++i) {
        v[i] = xr[i * 32 + lane];
        nz |= (v[i].x != 0.f) | (v[i].y != 0.f) | (v[i].z != 0.f) | (v[i].w != 0.f);
    }
    nz = __any_sync(0xffffffffu, nz);
    float* dst = g_Xp + (size_t)n * KNODE;
    const float4* nr = (const float4*)ne;
    #pragma unroll
    for (int i = 0; i < 4; ++i) {
        float4 w = nz ? v[i] : nr[i * 32 + lane];
        float4 r;
        r.x = tf32r(w.x); r.y = tf32r(w.y); r.z = tf32r(w.z); r.w = tf32r(w.w);
        *(float4*)(dst + (i * 32 + lane) * 4) = r;
    }
    if (lane < 10) {
        float di = fmaxf(g_deg_in[n], 1.f);
        float dv = fmaxf(g_deg_out[n], 1.f);
        float val = g_p[n * 10 + lane];
        if (lane >= 2 && lane < 6) val /= di;
        else if (lane >= 6) val /= dv;
        dst[512 + lane] = tf32r(val);
    } else {
        dst[512 + lane] = 0.f;   // pad cols 522..543
    }
}

// ---------------- node GEMM: g_G[N,1024] = g_Xp[N,544] @ g_Wnode[544,1024] ----
extern __shared__ float dynsmem[];

__global__ __launch_bounds__(256, 1) void node_gemm() {
    float* As = dynsmem;              // [2][BM][AS_STRIDE]
    float* Bs = dynsmem + 2 * ABUF;   // [2][BK][BS_STRIDE]

    const int tid = threadIdx.x;
    const int m0 = blockIdx.x * BM;
    const int n0 = blockIdx.y * BN;
    const int warp = tid >> 5, lane = tid & 31;
    const int wm = warp & 1, wn = warp >> 1;
    const int g = lane >> 2, t = lane & 3;
    const int KT = KNODE / BK;  // 17

    float acc[4][8][4];
    #pragma unroll
    for (int i = 0; i < 4; ++i)
        #pragma unroll
        for (int j = 0; j < 8; ++j)
            #pragma unroll
            for (int k = 0; k < 4; ++k) acc[i][j][k] = 0.f;

    // tile loaders
    auto loadA = [&](float* buf, int kbase) {
        #pragma unroll
        for (int i = 0; i < 4; ++i) {
            int id = i * 256 + tid;
            int row = id >> 3, c4 = id & 7;
            int n = m0 + row;
            const float* src = g_Xp + (size_t)n * KNODE + kbase + c4 * 4;
            cp16(buf + row * AS_STRIDE + c4 * 4, src, (n < NN) ? 16 : 0);
        }
    };
    auto loadB = [&](float* buf, int kbase) {
        #pragma unroll
        for (int i = 0; i < 8; ++i) {
            int id = i * 256 + tid;
            int row = id >> 6, c4 = id & 63;
            cp16(buf + row * BS_STRIDE + c4 * 4,
                 g_Wnode + (size_t)(kbase + row) * 1024 + n0 + c4 * 4, 16);
        }
    };

    loadA(As, 0); loadB(Bs, 0); cp_commit();

    for (int kt = 0; kt < KT; ++kt) {
        int cur = kt & 1;
        if (kt + 1 < KT) {
            loadA(As + (cur ^ 1) * ABUF, (kt + 1) * BK);
            loadB(Bs + (cur ^ 1) * BBUF, (kt + 1) * BK);
            cp_commit();
            asm volatile("cp.async.wait_group 1;" ::: "memory");
        } else {
            asm volatile("cp.async.wait_group 0;" ::: "memory");
        }
        __syncthreads();
        const float* Ab = As + cur * ABUF;
        const float* Bb = Bs + cur * BBUF;
        #pragma unroll
        for (int ks = 0; ks < 4; ++ks) {
            const int k0 = ks * 8;
            unsigned a[4][4], b[8][2];
            #pragma unroll
            for (int mf = 0; mf < 4; ++mf) {
                const float* ap = Ab + (wm * 64 + mf * 16 + g) * AS_STRIDE + k0 + t;
                a[mf][0] = __float_as_uint(ap[0]);
                a[mf][1] = __float_as_uint(ap[8 * AS_STRIDE]);
                a[mf][2] = __float_as_uint(ap[4]);
                a[mf][3] = __float_as_uint(ap[8 * AS_STRIDE + 4]);
            }
            #pragma unroll
            for (int nf = 0; nf < 8; ++nf) {
                const float* bp = Bb + (k0 + t) * BS_STRIDE + wn * 64 + nf * 8 + g;
                b[nf][0] = __float_as_uint(bp[0]);
                b[nf][1] = __float_as_uint(bp[4 * BS_STRIDE]);
            }
            #pragma unroll
            for (int mf = 0; mf < 4; ++mf)
                #pragma unroll
                for (int nf = 0; nf < 8; ++nf)
                    mma_tf32(acc[mf][nf], a[mf], b[nf]);
        }
        __syncthreads();
    }

    #pragma unroll
    for (int mf = 0; mf < 4; ++mf) {
        #pragma unroll
        for (int half = 0; half < 2; ++half) {
            int r = wm * 64 + mf * 16 + g + half * 8;
            int n = m0 + r;
            if (n < NN) {
                float* Gp = g_G + (size_t)n * 1024 + n0;
                #pragma unroll
                for (int nf = 0; nf < 8; ++nf) {
                    int cj = wn * 64 + nf * 8 + 2 * t;
                    *(float2*)&Gp[cj] = make_float2(acc[mf][nf][half * 2 + 0],
                                                    acc[mf][nf][half * 2 + 1]);
                }
            }
        }
    }
}

// ---------------- edge GEMM + fused gather/relu/W2 epilogue ------------------
__global__ __launch_bounds__(256, 1) void edge_gemm(
    const float* __restrict__ q_emb, const float* __restrict__ edge_attr,
    const int* __restrict__ srcI, const int* __restrict__ dstI,
    const float* __restrict__ b1, const float* __restrict__ W2,
    float* __restrict__ out)
{
    float* As = dynsmem;
    float* Bs = dynsmem + 2 * ABUF;
    __shared__ float sB1[BN];
    __shared__ float sW2[BN];

    const int tid = threadIdx.x;
    const int m0 = blockIdx.x * BM;
    const int n0 = blockIdx.y * BN;
    const int warp = tid >> 5, lane = tid & 31;
    const int wm = warp & 1, wn = warp >> 1;
    const int g = lane >> 2, t = lane & 3;
    const int KT = 1024 / BK;  // 32

    sB1[tid] = b1[n0 + tid];
    sW2[tid] = W2[n0 + tid];

    float acc[4][8][4];
    #pragma unroll
    for (int i = 0; i < 4; ++i)
        #pragma unroll
        for (int j = 0; j < 8; ++j)
            #pragma unroll
            for (int k = 0; k < 4; ++k) acc[i][j][k] = 0.f;

    auto loadA = [&](float* buf, int kbase) {
        #pragma unroll
        for (int i = 0; i < 4; ++i) {
            int id = i * 256 + tid;
            int row = id >> 3, c4 = id & 7;
            int e = m0 + row;
            int kg = kbase + c4 * 4;
            const float* src = (kg < 512) ? q_emb + (size_t)e * 512 + kg
                                          : edge_attr + (size_t)e * 512 + (kg - 512);
            cp16(buf + row * AS_STRIDE + c4 * 4, src, (e < EE) ? 16 : 0);
        }
    };
    auto loadB = [&](float* buf, int kbase) {
        #pragma unroll
        for (int i = 0; i < 8; ++i) {
            int id = i * 256 + tid;
            int row = id >> 6, c4 = id & 63;
            cp16(buf + row * BS_STRIDE + c4 * 4,
                 g_Wqa + (size_t)(kbase + row) * 512 + n0 + c4 * 4, 16);
        }
    };

    loadA(As, 0); loadB(Bs, 0); cp_commit();

    for (int kt = 0; kt < KT; ++kt) {
        int cur = kt & 1;
        if (kt + 1 < KT) {
            loadA(As + (cur ^ 1) * ABUF, (kt + 1) * BK);
            loadB(Bs + (cur ^ 1) * BBUF, (kt + 1) * BK);
            cp_commit();
            asm volatile("cp.async.wait_group 1;" ::: "memory");
        } else {
            asm volatile("cp.async.wait_group 0;" ::: "memory");
        }
        __syncthreads();
        const float* Ab = As + cur * ABUF;
        const float* Bb = Bs + cur * BBUF;
        #pragma unroll
        for (int ks = 0; ks < 4; ++ks) {
            const int k0 = ks * 8;
            unsigned a[4][4], b[8][2];
            #pragma unroll
            for (int mf = 0; mf < 4; ++mf) {
                const float* ap = Ab + (wm * 64 + mf * 16 + g) * AS_STRIDE + k0 + t;
                a[mf][0] = __float_as_uint(ap[0]);
                a[mf][1] = __float_as_uint(ap[8 * AS_STRIDE]);
                a[mf][2] = __float_as_uint(ap[4]);
                a[mf][3] = __float_as_uint(ap[8 * AS_STRIDE + 4]);
            }
            #pragma unroll
            for (int nf = 0; nf < 8; ++nf) {
                const float* bp = Bb + (k0 + t) * BS_STRIDE + wn * 64 + nf * 8 + g;
                b[nf][0] = __float_as_uint(bp[0]);
                b[nf][1] = __float_as_uint(bp[4 * BS_STRIDE]);
            }
            #pragma unroll
            for (int mf = 0; mf < 4; ++mf)
                #pragma unroll
                for (int nf = 0; nf < 8; ++nf)
                    mma_tf32(acc[mf][nf], a[mf], b[nf]);
        }
        __syncthreads();
    }

    // epilogue: z = acc + b1 + G_src[s] + G_dst[d]; relu; dot W2; atomic add
    #pragma unroll
    for (int mf = 0; mf < 4; ++mf) {
        #pragma unroll
        for (int half = 0; half < 2; ++half) {
            int r = wm * 64 + mf * 16 + g + half * 8;
            int e = m0 + r;
            float rowsum = 0.f;
            if (e < EE) {
                int s = srcI[e], d = dstI[e];
                const float* Gs = g_G + (size_t)s * 1024 + n0;
                const float* Gd = g_G + (size_t)d * 1024 + 512 + n0;
                #pragma unroll
                for (int nf = 0; nf < 8; ++nf) {
                    int cj = wn * 64 + nf * 8 + 2 * t;
                    float2 gs = *(const float2*)&Gs[cj];
                    float2 gd = *(const float2*)&Gd[cj];
                    float z0 = acc[mf][nf][half * 2 + 0] + sB1[cj] + gs.x + gd.x;
                    float z1 = acc[mf][nf][half * 2 + 1] + sB1[cj + 1] + gs.y + gd.y;
                    rowsum = fmaf(fmaxf(z0, 0.f), sW2[cj], rowsum);
                    rowsum = fmaf(fmaxf(z1, 0.f), sW2[cj + 1], rowsum);
                }
            }
            rowsum += __shfl_xor_sync(0xffffffffu, rowsum, 1);
            rowsum += __shfl_xor_sync(0xffffffffu, rowsum, 2);
            if (t == 0 && e < EE) atomicAdd(out + e, rowsum);
        }
    }
}

// ---------------- launch ------------------------------------------------------
extern "C" void kernel_launch(void* const* d_in, const int* in_sizes, int n_in,
                              void* d_out, int out_size) {
    const float* x     = (const float*)d_in[0];
    const int*   ei    = (const int*)d_in[1];
    const float* attr  = (const float*)d_in[2];
    const float* topic = (const float*)d_in[3];
    const float* qemb  = (const float*)d_in[4];
    const float* ne    = (const float*)d_in[5];
    const float* W1    = (const float*)d_in[6];
    const float* b1    = (const float*)d_in[7];
    const float* W2    = (const float*)d_in[8];
    const float* b2    = (const float*)d_in[9];
    float* out = (float*)d_out;
    const int* srcI = ei;
    const int* dstI = ei + EE;

    cudaFuncSetAttribute(node_gemm, cudaFuncAttributeMaxDynamicSharedMemorySize, SMEM_BYTES);
    cudaFuncSetAttribute(edge_gemm, cudaFuncAttributeMaxDynamicSharedMemorySize, SMEM_BYTES);

    const int WTOT = KNODE * 1024 + 1024 * 512;
    prep_w<<<(WTOT + 255) / 256, 256>>>(W1);
    init_all<<<(EE + 255) / 256, 256>>>(topic, b2, out);
    conv1<<<(EE + 255) / 256, 256>>>(srcI, dstI);
    conv2<<<(EE + 255) / 256, 256>>>(srcI, dstI);
    prep_xp<<<(NN * 32 + 255) / 256, 256>>>(x, ne);
    node_gemm<<<dim3((NN + BM - 1) / BM, 1024 / BN), 256, SMEM_BYTES>>>();
    edge_gemm<<<dim3((EE + BM - 1) / BM, 512 / BN), 256, SMEM_BYTES>>>(
        qemb, attr, srcI, dstI, b1, W2, out);
}